// round 15
// baseline (speedup 1.0000x reference)
#include <cuda_runtime.h>
#include <cuda_fp16.h>
#include <cstdint>

// Problem constants
#define BB 8
#define NN 8192
#define SS 2048
#define D1 256
#define D2 512
#define CIN 768
#define HH 512

typedef __half h16;

// ---------------- scratch (static device globals; no runtime alloc) ----------------
__device__ h16  g_P2T[(size_t)BB * SS * D2];           // fp16
__device__ int   g_idx[(size_t)BB * NN * 3];
__device__ float g_wgt[(size_t)BB * NN * 3];
__device__ h16  g_FT[(size_t)BB * NN * CIN];           // single fp16
__device__ h16  g_W0[HH * CIN];                        // single fp16
__device__ h16  g_W1[HH * HH];                         // single fp16
__device__ h16  g_X0[(size_t)BB * HH * NN];            // (b, c, n) fp16
__device__ float g_sum0[HH], g_sq0[HH], g_sum1[HH], g_sq1[HH];

// ======================= low-level helpers =======================
__device__ __forceinline__ uint32_t smem_u32(const void* p) {
    uint32_t a;
    asm("{ .reg .u64 t; cvta.to.shared.u64 t, %1; cvt.u32.u64 %0, t; }" : "=r"(a) : "l"(p));
    return a;
}
__device__ __forceinline__ void ldsm4(uint32_t& r0, uint32_t& r1, uint32_t& r2,
                                      uint32_t& r3, uint32_t a) {
    asm volatile("ldmatrix.sync.aligned.m8n8.x4.shared.b16 {%0,%1,%2,%3},[%4];"
                 : "=r"(r0), "=r"(r1), "=r"(r2), "=r"(r3) : "r"(a));
}
__device__ __forceinline__ void ldsm4t(uint32_t& r0, uint32_t& r1, uint32_t& r2,
                                       uint32_t& r3, uint32_t a) {
    asm volatile("ldmatrix.sync.aligned.m8n8.x4.trans.shared.b16 {%0,%1,%2,%3},[%4];"
                 : "=r"(r0), "=r"(r1), "=r"(r2), "=r"(r3) : "r"(a));
}
__device__ __forceinline__ void mma16816(float* d, const uint32_t* a, const uint32_t* b) {
    asm volatile(
        "mma.sync.aligned.m16n8k16.row.col.f32.f16.f16.f32 "
        "{%0,%1,%2,%3},{%4,%5,%6,%7},{%8,%9},{%0,%1,%2,%3};"
        : "+f"(d[0]), "+f"(d[1]), "+f"(d[2]), "+f"(d[3])
        : "r"(a[0]), "r"(a[1]), "r"(a[2]), "r"(a[3]), "r"(b[0]), "r"(b[1]));
}
__device__ __forceinline__ void cpa16(uint32_t dst, const void* src) {
    asm volatile("cp.async.cg.shared.global [%0],[%1],16;" :: "r"(dst), "l"(src));
}
#define CP_COMMIT() asm volatile("cp.async.commit_group;" ::: "memory")
#define CP_WAIT(n) asm volatile("cp.async.wait_group %0;" :: "n"(n) : "memory")

__device__ __forceinline__ uint32_t pack2h(h16 a, h16 b) {
    __half2 t = __halves2half2(a, b);
    return *reinterpret_cast<uint32_t*>(&t);
}
__device__ __forceinline__ float2 h2f2(uint32_t u) {
    return __half22float2(*reinterpret_cast<__half2*>(&u));
}

// ---------------- top-3 helper ----------------
struct Top3 { float d0, d1, d2; int i0, i1, i2; };
__device__ __forceinline__ void t3_ins(Top3& q, float t, int s) {
    if (t < q.d2) {
        if (t < q.d1) {
            q.d2 = q.d1; q.i2 = q.i1;
            if (t < q.d0) { q.d1 = q.d0; q.i1 = q.i0; q.d0 = t; q.i0 = s; }
            else          { q.d1 = t;    q.i1 = s; }
        } else { q.d2 = t; q.i2 = s; }
    }
}

// ======================= fused prep kernel =======================
#define NB_T3 128
#define NB_P2 8192
#define NB_P1 16384
#define NB_C0 (HH * CIN / 1024)
#define NB_C1 (HH * HH / 1024)
#define NB_TOTAL (NB_T3 + NB_P2 + NB_P1 + NB_C0 + NB_C1 + 1)

__global__ __launch_bounds__(256)
void prep_kernel(const float* __restrict__ xyz1, const float* __restrict__ xyz2,
                 const float* __restrict__ p1, const float* __restrict__ p2,
                 const float* __restrict__ w0g, const float* __restrict__ w1g) {
    __shared__ float sh[8192];
    int r = blockIdx.x;
    const int tid = threadIdx.x;

    if (r < NB_T3) {
        float* sx = sh;
        float* sy = sh + 2048;
        float* sz = sh + 4096;
        float* sn = sh + 6144;
        const int b = r >> 4;
        const int nbase = (r & 15) * 512;

        for (int i = tid; i < SS; i += 256) {
            float x = xyz2[((size_t)b * 3 + 0) * SS + i];
            float y = xyz2[((size_t)b * 3 + 1) * SS + i];
            float z = xyz2[((size_t)b * 3 + 2) * SS + i];
            sx[i] = x; sy[i] = y; sz[i] = z;
            sn[i] = x * x + y * y + z * z;
        }
        __syncthreads();

        const int na = nbase + tid;
        const int nb = nbase + 256 + tid;
        float xa = xyz1[((size_t)b * 3 + 0) * NN + na];
        float ya = xyz1[((size_t)b * 3 + 1) * NN + na];
        float za = xyz1[((size_t)b * 3 + 2) * NN + na];
        float xb = xyz1[((size_t)b * 3 + 0) * NN + nb];
        float yb = xyz1[((size_t)b * 3 + 1) * NN + nb];
        float zb = xyz1[((size_t)b * 3 + 2) * NN + nb];
        float n1a = xa * xa + ya * ya + za * za;
        float n1b = xb * xb + yb * yb + zb * zb;
        float mxa = -2.f * xa, mya = -2.f * ya, mza = -2.f * za;
        float mxb = -2.f * xb, myb = -2.f * yb, mzb = -2.f * zb;

        Top3 qa = {3.4e38f, 3.4e38f, 3.4e38f, 0, 0, 0};
        Top3 qb = {3.4e38f, 3.4e38f, 3.4e38f, 0, 0, 0};

        for (int s = 0; s < SS; s += 4) {
            float4 vx = ((float4*)sx)[s >> 2], vy = ((float4*)sy)[s >> 2];
            float4 vz = ((float4*)sz)[s >> 2], vn = ((float4*)sn)[s >> 2];
            float t;
            t = fmaf(mxa, vx.x, vn.x); t = fmaf(mya, vy.x, t); t = fmaf(mza, vz.x, t); t3_ins(qa, t, s + 0);
            t = fmaf(mxa, vx.y, vn.y); t = fmaf(mya, vy.y, t); t = fmaf(mza, vz.y, t); t3_ins(qa, t, s + 1);
            t = fmaf(mxa, vx.z, vn.z); t = fmaf(mya, vy.z, t); t = fmaf(mza, vz.z, t); t3_ins(qa, t, s + 2);
            t = fmaf(mxa, vx.w, vn.w); t = fmaf(mya, vy.w, t); t = fmaf(mza, vz.w, t); t3_ins(qa, t, s + 3);
            t = fmaf(mxb, vx.x, vn.x); t = fmaf(myb, vy.x, t); t = fmaf(mzb, vz.x, t); t3_ins(qb, t, s + 0);
            t = fmaf(mxb, vx.y, vn.y); t = fmaf(myb, vy.y, t); t = fmaf(mzb, vz.y, t); t3_ins(qb, t, s + 1);
            t = fmaf(mxb, vx.z, vn.z); t = fmaf(myb, vy.z, t); t = fmaf(mzb, vz.z, t); t3_ins(qb, t, s + 2);
            t = fmaf(mxb, vx.w, vn.w); t = fmaf(myb, vy.w, t); t = fmaf(mzb, vz.w, t); t3_ins(qb, t, s + 3);
        }

        {
            size_t base = ((size_t)b * NN + na) * 3;
            float d0 = qa.d0 + n1a, d1 = qa.d1 + n1a, d2 = qa.d2 + n1a;
            float w0 = 1.0f / (d0 + 1e-8f), w1 = 1.0f / (d1 + 1e-8f), w2 = 1.0f / (d2 + 1e-8f);
            float inv = 1.0f / (w0 + w1 + w2);
            g_idx[base + 0] = qa.i0; g_idx[base + 1] = qa.i1; g_idx[base + 2] = qa.i2;
            g_wgt[base + 0] = w0 * inv; g_wgt[base + 1] = w1 * inv; g_wgt[base + 2] = w2 * inv;
        }
        {
            size_t base = ((size_t)b * NN + nb) * 3;
            float d0 = qb.d0 + n1b, d1 = qb.d1 + n1b, d2 = qb.d2 + n1b;
            float w0 = 1.0f / (d0 + 1e-8f), w1 = 1.0f / (d1 + 1e-8f), w2 = 1.0f / (d2 + 1e-8f);
            float inv = 1.0f / (w0 + w1 + w2);
            g_idx[base + 0] = qb.i0; g_idx[base + 1] = qb.i1; g_idx[base + 2] = qb.i2;
            g_wgt[base + 0] = w0 * inv; g_wgt[base + 1] = w1 * inv; g_wgt[base + 2] = w2 * inv;
        }
        return;
    }
    r -= NB_T3;
    if (r < NB_P2) {
        int b = r >> 10, y = (r >> 6) & 15, x = r & 63;
        int c0 = y * 32, s0 = x * 32;
        int tx = tid & 31, ty = tid >> 5;
        float (*t)[33] = (float(*)[33])sh;
#pragma unroll
        for (int j = ty; j < 32; j += 8)
            t[j][tx] = p2[((size_t)b * D2 + c0 + j) * SS + s0 + tx];
        __syncthreads();
#pragma unroll
        for (int j = ty; j < 32; j += 8)
            g_P2T[((size_t)b * SS + s0 + j) * D2 + c0 + tx] = __float2half_rn(t[tx][j]);
        return;
    }
    r -= NB_P2;
    if (r < NB_P1) {
        int b = r >> 11, y = (r >> 8) & 7, x = r & 255;
        int c0 = y * 32, n0 = x * 32;
        int tx = tid & 31, ty = tid >> 5;
        float (*t)[33] = (float(*)[33])sh;
#pragma unroll
        for (int j = ty; j < 32; j += 8)
            t[j][tx] = p1[((size_t)b * D1 + c0 + j) * NN + n0 + tx];
        __syncthreads();
#pragma unroll
        for (int j = ty; j < 32; j += 8) {
            size_t off = ((size_t)b * NN + n0 + j) * CIN + c0 + tx;
            g_FT[off] = __float2half_rn(t[tx][j]);
        }
        return;
    }
    r -= NB_P1;
    if (r < NB_C0 + NB_C1) {
        const float* src;
        h16* dst;
        int i;
        if (r < NB_C0) { src = w0g; dst = g_W0; i = r * 1024 + tid * 4; }
        else { src = w1g; dst = g_W1; i = (r - NB_C0) * 1024 + tid * 4; }
        float4 v = *(const float4*)(src + i);
        *(uint2*)&dst[i] = make_uint2(
            pack2h(__float2half_rn(v.x), __float2half_rn(v.y)),
            pack2h(__float2half_rn(v.z), __float2half_rn(v.w)));
        return;
    }
    if (tid < 256) {
        g_sum0[tid] = 0.f; g_sum0[tid + 256] = 0.f;
        g_sq0[tid] = 0.f;  g_sq0[tid + 256] = 0.f;
        g_sum1[tid] = 0.f; g_sum1[tid + 256] = 0.f;
        g_sq1[tid] = 0.f;  g_sq1[tid + 256] = 0.f;
    }
}

// ---------------- gather + interpolate -> g_FT[:, :, 256:768] (uint4 vectorized) ----------------
__global__ void gather_kernel() {
    int wglob = blockIdx.x * 8 + (threadIdx.x >> 5);
    int lane = threadIdx.x & 31;
    int b = wglob / NN;
    size_t base = (size_t)wglob * 3;
    int i0 = g_idx[base + 0], i1 = g_idx[base + 1], i2 = g_idx[base + 2];
    float w0 = g_wgt[base + 0], w1 = g_wgt[base + 1], w2 = g_wgt[base + 2];
    const h16* r0 = g_P2T + ((size_t)b * SS + i0) * D2;
    const h16* r1 = g_P2T + ((size_t)b * SS + i1) * D2;
    const h16* r2 = g_P2T + ((size_t)b * SS + i2) * D2;
    size_t dbase = (size_t)wglob * CIN + D1;
#pragma unroll
    for (int c = lane * 8; c < D2; c += 256) {
        uint4 u0 = *(const uint4*)&r0[c];
        uint4 u1 = *(const uint4*)&r1[c];
        uint4 u2 = *(const uint4*)&r2[c];
        uint4 o;
        uint32_t* up0 = (uint32_t*)&u0;
        uint32_t* up1 = (uint32_t*)&u1;
        uint32_t* up2 = (uint32_t*)&u2;
        uint32_t* op = (uint32_t*)&o;
#pragma unroll
        for (int j = 0; j < 4; j++) {
            float2 a = h2f2(up0[j]), d = h2f2(up1[j]), e = h2f2(up2[j]);
            float y0 = w0 * a.x + w1 * d.x + w2 * e.x;
            float y1 = w0 * a.y + w1 * d.y + w2 * e.y;
            op[j] = pack2h(__float2half_rn(y0), __float2half_rn(y1));
        }
        *(uint4*)&g_FT[dbase + c] = o;
    }
}

// ======================= HMMA GEMM 1 (fp16, K-chunk 96, ring-2) =======================
#define T1B 26624                         // 128 rows x 208B (96 fp16 + 8 pad)
#define ST1 (2 * T1B)                     // stage: A, B = 53248
static constexpr int G1_SMEM = 2 * ST1;   // 106496 -> 2 CTAs/SM (213KB < 227KB)

__global__ __launch_bounds__(256, 2)
void hmma_gemm1(const h16* __restrict__ Ag, const h16* __restrict__ Bg,
                const float* __restrict__ bias, h16* __restrict__ out) {
    extern __shared__ char smem[];
    const uint32_t sb = smem_u32(smem);
    const int tid = threadIdx.x, lane = tid & 31, wid = tid >> 5;
    const int m0 = blockIdx.x * 128, n0 = blockIdx.y * 128, b = blockIdx.z;
    const int wm = (wid & 3) * 32, wn = (wid >> 2) * 64;

    const h16* Arow = Ag + (size_t)m0 * CIN;
    const h16* Brow = Bg + ((size_t)b * NN + n0) * CIN;

    float acc[2][8][4];
#pragma unroll
    for (int i = 0; i < 2; i++)
#pragma unroll
        for (int j = 0; j < 8; j++)
#pragma unroll
            for (int q = 0; q < 4; q++) acc[i][j][q] = 0.f;

    auto issue = [&](int kc) {
        const int kb = kc * 96;
        const uint32_t sbuf = sb + (kc & 1) * ST1;
#pragma unroll
        for (int t = 0; t < 6; t++) {
            int idx = tid + t * 256;           // 1536 segments of 16B per tensor
            int row = idx / 12, seg = idx % 12;
            uint32_t d = sbuf + row * 208 + seg * 16;
            cpa16(d,       Arow + (size_t)row * CIN + kb + seg * 8);
            cpa16(d + T1B, Brow + (size_t)row * CIN + kb + seg * 8);
        }
        CP_COMMIT();
    };

    const int KT = CIN / 96;   // 8
    issue(0);

    for (int c = 0; c < KT; c++) {
        const int buf = c & 1;
        if (c + 1 < KT) {
            issue(c + 1);
            CP_WAIT(1);
        } else {
            CP_WAIT(0);
        }
        __syncthreads();

        const uint32_t sA = sb + buf * ST1;
        const uint32_t sB = sA + T1B;
#pragma unroll
        for (int ks = 0; ks < 6; ks++) {
            const int k16 = ks * 16;
            uint32_t ah[2][4];
#pragma unroll
            for (int mi = 0; mi < 2; mi++) {
                uint32_t ad = sA + (wm + mi * 16 + (lane & 15)) * 208
                                 + (k16 + ((lane >> 4) << 3)) * 2;
                ldsm4(ah[mi][0], ah[mi][1], ah[mi][2], ah[mi][3], ad);
            }
#pragma unroll
            for (int ng = 0; ng < 4; ng++) {
                uint32_t row = wn + ng * 16 + (lane & 7) + ((lane & 16) >> 1);
                uint32_t col = k16 + (lane & 8);
                uint32_t ad = sB + row * 208 + col * 2;
                uint32_t bh[4];
                ldsm4(bh[0], bh[1], bh[2], bh[3], ad);
#pragma unroll
                for (int mi = 0; mi < 2; mi++) {
                    mma16816(acc[mi][2 * ng],     ah[mi], bh);
                    mma16816(acc[mi][2 * ng + 1], ah[mi], bh + 2);
                }
            }
        }
        __syncthreads();
    }

    // epilogue -> out fp16 (b, m, n) + bias, fused channel stats via atomics
    const int gq = lane >> 2, tq = lane & 3;
#pragma unroll
    for (int mi = 0; mi < 2; mi++) {
        int r0 = m0 + wm + mi * 16 + gq;
        float bv0 = bias[r0], bv1 = bias[r0 + 8];
        h16* o0 = out + ((size_t)b * HH + r0) * NN;
        h16* o1 = o0 + (size_t)8 * NN;
        float s0 = 0.f, q0 = 0.f, s1 = 0.f, q1 = 0.f;
#pragma unroll
        for (int ni = 0; ni < 8; ni++) {
            int cc = n0 + wn + ni * 8 + tq * 2;
            float y0 = acc[mi][ni][0] + bv0, y1 = acc[mi][ni][1] + bv0;
            float y2 = acc[mi][ni][2] + bv1, y3 = acc[mi][ni][3] + bv1;
            *(uint32_t*)&o0[cc] = pack2h(__float2half_rn(y0), __float2half_rn(y1));
            *(uint32_t*)&o1[cc] = pack2h(__float2half_rn(y2), __float2half_rn(y3));
            s0 += y0 + y1; q0 += y0 * y0 + y1 * y1;
            s1 += y2 + y3; q1 += y2 * y2 + y3 * y3;
        }
#pragma unroll
        for (int o = 1; o <= 2; o <<= 1) {
            s0 += __shfl_xor_sync(~0u, s0, o);
            q0 += __shfl_xor_sync(~0u, q0, o);
            s1 += __shfl_xor_sync(~0u, s1, o);
            q1 += __shfl_xor_sync(~0u, q1, o);
        }
        if (tq == 0) {
            atomicAdd(&g_sum0[r0], s0);     atomicAdd(&g_sq0[r0], q0);
            atomicAdd(&g_sum0[r0 + 8], s1); atomicAdd(&g_sq0[r0 + 8], q1);
        }
    }
}

// ======================= HMMA GEMM 2 (fp16, K-chunk 64, in-kernel BN coeffs) =======================
#define AT2 18432                // A stage: 128 x 144B
#define BT2 17408                // B stage: 64 k-rows x 272B
#define SC2_OFF (2 * AT2 + 2 * BT2)                  // 71680
static constexpr int G2_SMEM = SC2_OFF + 2 * HH * 4; // 75776 -> 2 CTAs/SM

__global__ __launch_bounds__(256, 2)
void hmma_gemm2(const h16* __restrict__ Ag,
                const h16* __restrict__ X0,
                const float* __restrict__ gsum, const float* __restrict__ gsq,
                const float* __restrict__ g0, const float* __restrict__ be0,
                const float* __restrict__ bias, float* __restrict__ out) {
    extern __shared__ char smem[];
    const uint32_t sb = smem_u32(smem);
    const int tid = threadIdx.x, lane = tid & 31, wid = tid >> 5;
    const int m0 = blockIdx.x * 128, n0 = blockIdx.y * 128, b = blockIdx.z;
    const int wm = (wid & 3) * 32, wn = (wid >> 2) * 64;

    float* sScale = (float*)(smem + SC2_OFF);
    float* sShift = sScale + HH;

    const h16* Arow = Ag + (size_t)m0 * HH;
    const h16* Xb = X0 + (size_t)b * HH * NN + n0;

    float acc[2][8][4];
#pragma unroll
    for (int i = 0; i < 2; i++)
#pragma unroll
        for (int j = 0; j < 8; j++)
#pragma unroll
            for (int q = 0; q < 4; q++) acc[i][j][q] = 0.f;

    const int brow = tid >> 3, bcol = (tid & 7) * 16;
    uint4 xr[2][2];
    float scl[2], shf[2];

    const int row_l = tid >> 3, seg = tid & 7;
    auto issueA = [&](int kc) {
        const int kb = kc * 64;
        const uint32_t sbuf = sb + (kc & 1) * AT2;
#pragma unroll
        for (int t = 0; t < 4; t++) {
            int row = row_l + t * 32;
            uint32_t d = sbuf + row * 144 + seg * 16;
            cpa16(d, Arow + (size_t)row * HH + kb + seg * 8);
        }
        CP_COMMIT();
    };
    auto loadX = [&](int kb) {
#pragma unroll
        for (int half = 0; half < 2; half++) {
            int k = kb + brow + half * 32;
            const h16* src = Xb + (size_t)k * NN + bcol;
            xr[half][0] = *(const uint4*)src;
            xr[half][1] = *(const uint4*)(src + 8);
            scl[half] = sScale[k];
            shf[half] = sShift[k];
        }
    };

    // prologue: BN coefficients for layer 0 -> smem
    {
        const float inv = 1.f / (float)(BB * NN);
#pragma unroll
        for (int i = tid; i < HH; i += 256) {
            float m = gsum[i] * inv;
            float var = gsq[i] * inv - m * m;
            float sc = g0[i] * rsqrtf(var + 1e-5f);
            sScale[i] = sc;
            sShift[i] = be0[i] - m * sc;
        }
        issueA(0);
        __syncthreads();   // sScale/sShift visible before loadX
        loadX(0);
    }

    const uint32_t sBoff = 2 * AT2;
    const int KT = HH / 64;  // 8
    for (int c = 0; c < KT; c++) {
        const int buf = c & 1;
        // STS-transform chunk c into B buf (64 k-rows x 128 n)
        {
#pragma unroll
            for (int half = 0; half < 2; half++) {
                uint32_t doff = sBoff + buf * BT2 + (brow + half * 32) * 272 + bcol * 2;
                float s = scl[half], h = shf[half];
#pragma unroll
                for (int j = 0; j < 4; j++) {
                    float2 p = h2f2(j < 2 ? (j == 0 ? xr[half][0].x : xr[half][0].z)
                                          : (j == 2 ? xr[half][1].x : xr[half][1].z));
                    float2 q = h2f2(j < 2 ? (j == 0 ? xr[half][0].y : xr[half][0].w)
                                          : (j == 2 ? xr[half][1].y : xr[half][1].w));
                    float y0 = fmaxf(fmaf(p.x, s, h), 0.f);
                    float y1 = fmaxf(fmaf(p.y, s, h), 0.f);
                    float y2 = fmaxf(fmaf(q.x, s, h), 0.f);
                    float y3 = fmaxf(fmaf(q.y, s, h), 0.f);
                    *(uint2*)(smem + doff + j * 8) = make_uint2(
                        pack2h(__float2half_rn(y0), __float2half_rn(y1)),
                        pack2h(__float2half_rn(y2), __float2half_rn(y3)));
                }
            }
        }
        if (c + 1 < KT) {
            issueA(c + 1);
            loadX((c + 1) * 64);
            CP_WAIT(1);
        } else {
            CP_WAIT(0);
        }
        __syncthreads();

        const uint32_t sA = sb + buf * AT2;
        const uint32_t sB = sb + sBoff + buf * BT2;
#pragma unroll
        for (int ks = 0; ks < 4; ks++) {
            const int k16 = ks * 16;
            uint32_t ah[2][4];
#pragma unroll
            for (int mi = 0; mi < 2; mi++) {
                uint32_t ad = sA + (wm + mi * 16 + (lane & 15)) * 144
                                 + (k16 + ((lane >> 4) << 3)) * 2;
                ldsm4(ah[mi][0], ah[mi][1], ah[mi][2], ah[mi][3], ad);
            }
#pragma unroll
            for (int ng = 0; ng < 4; ng++) {
                uint32_t row = k16 + (lane & 7) + (lane & 8);
                uint32_t col = wn + ng * 16 + ((lane >> 4) << 3);
                uint32_t ad = sB + row * 272 + col * 2;
                uint32_t bh[4];
                ldsm4t(bh[0], bh[1], bh[2], bh[3], ad);
#pragma unroll
                for (int mi = 0; mi < 2; mi++) {
                    mma16816(acc[mi][2 * ng],     ah[mi], bh);
                    mma16816(acc[mi][2 * ng + 1], ah[mi], bh + 2);
                }
            }
        }
        __syncthreads();
    }

    const int gq = lane >> 2, tq = lane & 3;
#pragma unroll
    for (int mi = 0; mi < 2; mi++) {
        int r0 = m0 + wm + mi * 16 + gq;
        float bv0 = bias[r0], bv1 = bias[r0 + 8];
        float* o0 = out + ((size_t)b * HH + r0) * NN;
        float* o1 = o0 + (size_t)8 * NN;
        float s0 = 0.f, q0 = 0.f, s1 = 0.f, q1 = 0.f;
#pragma unroll
        for (int ni = 0; ni < 8; ni++) {
            int cc = n0 + wn + ni * 8 + tq * 2;
            float y0 = acc[mi][ni][0] + bv0, y1 = acc[mi][ni][1] + bv0;
            float y2 = acc[mi][ni][2] + bv1, y3 = acc[mi][ni][3] + bv1;
            *(float2*)&o0[cc] = make_float2(y0, y1);
            *(float2*)&o1[cc] = make_float2(y2, y3);
            s0 += y0 + y1; q0 += y0 * y0 + y1 * y1;
            s1 += y2 + y3; q1 += y2 * y2 + y3 * y3;
        }
#pragma unroll
        for (int o = 1; o <= 2; o <<= 1) {
            s0 += __shfl_xor_sync(~0u, s0, o);
            q0 += __shfl_xor_sync(~0u, q0, o);
            s1 += __shfl_xor_sync(~0u, s1, o);
            q1 += __shfl_xor_sync(~0u, q1, o);
        }
        if (tq == 0) {
            atomicAdd(&g_sum1[r0], s0);     atomicAdd(&g_sq1[r0], q0);
            atomicAdd(&g_sum1[r0 + 8], s1); atomicAdd(&g_sq1[r0 + 8], q1);
        }
    }
}

// ---------------- apply BN layer1 (coeffs computed in-kernel) ----------------
__global__ __launch_bounds__(256)
void apply_bn_kernel(float* __restrict__ X,
                     const float* __restrict__ g1, const float* __restrict__ be1) {
    __shared__ float sScale[HH], sShift[HH];
    const float inv = 1.f / (float)(BB * NN);
#pragma unroll
    for (int i = threadIdx.x; i < HH; i += 256) {
        float m = g_sum1[i] * inv;
        float var = g_sq1[i] * inv - m * m;
        float sc = g1[i] * rsqrtf(var + 1e-5f);
        sScale[i] = sc;
        sShift[i] = be1[i] - m * sc;
    }
    __syncthreads();
    const size_t total4 = (size_t)BB * HH * NN / 4;
    for (size_t i = (size_t)blockIdx.x * blockDim.x + threadIdx.x; i < total4;
         i += (size_t)gridDim.x * blockDim.x) {
        float4 v = __ldcs(&((float4*)X)[i]);
        int c = (int)((i * 4) >> 13) & (HH - 1);
        float s = sScale[c], h = sShift[c];
        v.x = fmaxf(fmaf(v.x, s, h), 0.f);
        v.y = fmaxf(fmaf(v.y, s, h), 0.f);
        v.z = fmaxf(fmaf(v.z, s, h), 0.f);
        v.w = fmaxf(fmaf(v.w, s, h), 0.f);
        __stcs(&((float4*)X)[i], v);
    }
}

// ======================= launcher =======================
extern "C" void kernel_launch(void* const* d_in, const int* in_sizes, int n_in,
                              void* d_out, int out_size) {
    const float* xyz1    = (const float*)d_in[0];
    const float* xyz2    = (const float*)d_in[1];
    const float* points1 = (const float*)d_in[2];
    const float* points2 = (const float*)d_in[3];
    const float* w0 = (const float*)d_in[4];
    const float* b0 = (const float*)d_in[5];
    const float* g0 = (const float*)d_in[6];
    const float* be0 = (const float*)d_in[7];
    const float* w1 = (const float*)d_in[8];
    const float* b1 = (const float*)d_in[9];
    const float* g1 = (const float*)d_in[10];
    const float* be1 = (const float*)d_in[11];
    float* out = (float*)d_out;

    float *p_sum0, *p_sq0;
    h16 *p_W0, *p_W1, *p_FT, *p_X0;
    cudaGetSymbolAddress((void**)&p_X0, g_X0);
    cudaGetSymbolAddress((void**)&p_sum0, g_sum0);
    cudaGetSymbolAddress((void**)&p_sq0, g_sq0);
    cudaGetSymbolAddress((void**)&p_W0, g_W0);
    cudaGetSymbolAddress((void**)&p_W1, g_W1);
    cudaGetSymbolAddress((void**)&p_FT, g_FT);

    cudaFuncSetAttribute(hmma_gemm1, cudaFuncAttributeMaxDynamicSharedMemorySize, G1_SMEM);
    cudaFuncSetAttribute(hmma_gemm2, cudaFuncAttributeMaxDynamicSharedMemorySize, G2_SMEM);

    prep_kernel<<<NB_TOTAL, 256>>>(xyz1, xyz2, points1, points2, w0, w1);
    gather_kernel<<<BB * NN / 8, 256>>>();

    hmma_gemm1<<<dim3(HH / 128, NN / 128, BB), 256, G1_SMEM>>>(
        p_W0, p_FT, b0, p_X0);

    hmma_gemm2<<<dim3(HH / 128, NN / 128, BB), 256, G2_SMEM>>>(
        p_W1, p_X0, p_sum0, p_sq0, g0, be0, b1, out);

    apply_bn_kernel<<<4096, 256>>>(out, g1, be1);
}

// round 16
// speedup vs baseline: 1.0380x; 1.0380x over previous
#include <cuda_runtime.h>
#include <cuda_fp16.h>
#include <cstdint>

// Problem constants
#define BB 8
#define NN 8192
#define SS 2048
#define D1 256
#define D2 512
#define CIN 768
#define HH 512

typedef __half h16;

// ---------------- scratch (static device globals; no runtime alloc) ----------------
__device__ h16  g_P2T[(size_t)BB * SS * D2];           // fp16
__device__ int   g_idx[(size_t)BB * NN * 3];
__device__ float g_wgt[(size_t)BB * NN * 3];
__device__ h16  g_FT[(size_t)BB * NN * CIN];           // single fp16
__device__ h16  g_W0[HH * CIN];                        // single fp16
__device__ h16  g_W1[HH * HH];                         // single fp16
__device__ h16  g_X0[(size_t)BB * HH * NN];            // (b, c, n) fp16
__device__ float g_sum0[HH], g_sq0[HH], g_sum1[HH], g_sq1[HH];

// ======================= low-level helpers =======================
__device__ __forceinline__ uint32_t smem_u32(const void* p) {
    uint32_t a;
    asm("{ .reg .u64 t; cvta.to.shared.u64 t, %1; cvt.u32.u64 %0, t; }" : "=r"(a) : "l"(p));
    return a;
}
__device__ __forceinline__ void ldsm4(uint32_t& r0, uint32_t& r1, uint32_t& r2,
                                      uint32_t& r3, uint32_t a) {
    asm volatile("ldmatrix.sync.aligned.m8n8.x4.shared.b16 {%0,%1,%2,%3},[%4];"
                 : "=r"(r0), "=r"(r1), "=r"(r2), "=r"(r3) : "r"(a));
}
__device__ __forceinline__ void ldsm4t(uint32_t& r0, uint32_t& r1, uint32_t& r2,
                                       uint32_t& r3, uint32_t a) {
    asm volatile("ldmatrix.sync.aligned.m8n8.x4.trans.shared.b16 {%0,%1,%2,%3},[%4];"
                 : "=r"(r0), "=r"(r1), "=r"(r2), "=r"(r3) : "r"(a));
}
__device__ __forceinline__ void mma16816(float* d, const uint32_t* a, const uint32_t* b) {
    asm volatile(
        "mma.sync.aligned.m16n8k16.row.col.f32.f16.f16.f32 "
        "{%0,%1,%2,%3},{%4,%5,%6,%7},{%8,%9},{%0,%1,%2,%3};"
        : "+f"(d[0]), "+f"(d[1]), "+f"(d[2]), "+f"(d[3])
        : "r"(a[0]), "r"(a[1]), "r"(a[2]), "r"(a[3]), "r"(b[0]), "r"(b[1]));
}
__device__ __forceinline__ void cpa16(uint32_t dst, const void* src) {
    asm volatile("cp.async.cg.shared.global [%0],[%1],16;" :: "r"(dst), "l"(src));
}
#define CP_COMMIT() asm volatile("cp.async.commit_group;" ::: "memory")
#define CP_WAIT(n) asm volatile("cp.async.wait_group %0;" :: "n"(n) : "memory")

__device__ __forceinline__ uint32_t pack2h(h16 a, h16 b) {
    __half2 t = __halves2half2(a, b);
    return *reinterpret_cast<uint32_t*>(&t);
}
__device__ __forceinline__ float2 h2f2(uint32_t u) {
    return __half22float2(*reinterpret_cast<__half2*>(&u));
}

// ---------------- top-3 helper ----------------
struct Top3 { float d0, d1, d2; int i0, i1, i2; };
__device__ __forceinline__ void t3_ins(Top3& q, float t, int s) {
    if (t < q.d2) {
        if (t < q.d1) {
            q.d2 = q.d1; q.i2 = q.i1;
            if (t < q.d0) { q.d1 = q.d0; q.i1 = q.i0; q.d0 = t; q.i0 = s; }
            else          { q.d1 = t;    q.i1 = s; }
        } else { q.d2 = t; q.i2 = s; }
    }
}

// ======================= fused prep kernel =======================
#define NB_T3 128
#define NB_P2 8192
#define NB_P1 16384
#define NB_C0 (HH * CIN / 1024)
#define NB_C1 (HH * HH / 1024)
#define NB_TOTAL (NB_T3 + NB_P2 + NB_P1 + NB_C0 + NB_C1 + 1)

__global__ __launch_bounds__(256)
void prep_kernel(const float* __restrict__ xyz1, const float* __restrict__ xyz2,
                 const float* __restrict__ p1, const float* __restrict__ p2,
                 const float* __restrict__ w0g, const float* __restrict__ w1g) {
    __shared__ float sh[8192];
    int r = blockIdx.x;
    const int tid = threadIdx.x;

    if (r < NB_T3) {
        float* sx = sh;
        float* sy = sh + 2048;
        float* sz = sh + 4096;
        float* sn = sh + 6144;
        const int b = r >> 4;
        const int nbase = (r & 15) * 512;

        for (int i = tid; i < SS; i += 256) {
            float x = xyz2[((size_t)b * 3 + 0) * SS + i];
            float y = xyz2[((size_t)b * 3 + 1) * SS + i];
            float z = xyz2[((size_t)b * 3 + 2) * SS + i];
            sx[i] = x; sy[i] = y; sz[i] = z;
            sn[i] = x * x + y * y + z * z;
        }
        __syncthreads();

        const int na = nbase + tid;
        const int nb = nbase + 256 + tid;
        float xa = xyz1[((size_t)b * 3 + 0) * NN + na];
        float ya = xyz1[((size_t)b * 3 + 1) * NN + na];
        float za = xyz1[((size_t)b * 3 + 2) * NN + na];
        float xb = xyz1[((size_t)b * 3 + 0) * NN + nb];
        float yb = xyz1[((size_t)b * 3 + 1) * NN + nb];
        float zb = xyz1[((size_t)b * 3 + 2) * NN + nb];
        float n1a = xa * xa + ya * ya + za * za;
        float n1b = xb * xb + yb * yb + zb * zb;
        float mxa = -2.f * xa, mya = -2.f * ya, mza = -2.f * za;
        float mxb = -2.f * xb, myb = -2.f * yb, mzb = -2.f * zb;

        Top3 qa = {3.4e38f, 3.4e38f, 3.4e38f, 0, 0, 0};
        Top3 qb = {3.4e38f, 3.4e38f, 3.4e38f, 0, 0, 0};

        for (int s = 0; s < SS; s += 4) {
            float4 vx = ((float4*)sx)[s >> 2], vy = ((float4*)sy)[s >> 2];
            float4 vz = ((float4*)sz)[s >> 2], vn = ((float4*)sn)[s >> 2];
            float t;
            t = fmaf(mxa, vx.x, vn.x); t = fmaf(mya, vy.x, t); t = fmaf(mza, vz.x, t); t3_ins(qa, t, s + 0);
            t = fmaf(mxa, vx.y, vn.y); t = fmaf(mya, vy.y, t); t = fmaf(mza, vz.y, t); t3_ins(qa, t, s + 1);
            t = fmaf(mxa, vx.z, vn.z); t = fmaf(mya, vy.z, t); t = fmaf(mza, vz.z, t); t3_ins(qa, t, s + 2);
            t = fmaf(mxa, vx.w, vn.w); t = fmaf(mya, vy.w, t); t = fmaf(mza, vz.w, t); t3_ins(qa, t, s + 3);
            t = fmaf(mxb, vx.x, vn.x); t = fmaf(myb, vy.x, t); t = fmaf(mzb, vz.x, t); t3_ins(qb, t, s + 0);
            t = fmaf(mxb, vx.y, vn.y); t = fmaf(myb, vy.y, t); t = fmaf(mzb, vz.y, t); t3_ins(qb, t, s + 1);
            t = fmaf(mxb, vx.z, vn.z); t = fmaf(myb, vy.z, t); t = fmaf(mzb, vz.z, t); t3_ins(qb, t, s + 2);
            t = fmaf(mxb, vx.w, vn.w); t = fmaf(myb, vy.w, t); t = fmaf(mzb, vz.w, t); t3_ins(qb, t, s + 3);
        }

        {
            size_t base = ((size_t)b * NN + na) * 3;
            float d0 = qa.d0 + n1a, d1 = qa.d1 + n1a, d2 = qa.d2 + n1a;
            float w0 = 1.0f / (d0 + 1e-8f), w1 = 1.0f / (d1 + 1e-8f), w2 = 1.0f / (d2 + 1e-8f);
            float inv = 1.0f / (w0 + w1 + w2);
            g_idx[base + 0] = qa.i0; g_idx[base + 1] = qa.i1; g_idx[base + 2] = qa.i2;
            g_wgt[base + 0] = w0 * inv; g_wgt[base + 1] = w1 * inv; g_wgt[base + 2] = w2 * inv;
        }
        {
            size_t base = ((size_t)b * NN + nb) * 3;
            float d0 = qb.d0 + n1b, d1 = qb.d1 + n1b, d2 = qb.d2 + n1b;
            float w0 = 1.0f / (d0 + 1e-8f), w1 = 1.0f / (d1 + 1e-8f), w2 = 1.0f / (d2 + 1e-8f);
            float inv = 1.0f / (w0 + w1 + w2);
            g_idx[base + 0] = qb.i0; g_idx[base + 1] = qb.i1; g_idx[base + 2] = qb.i2;
            g_wgt[base + 0] = w0 * inv; g_wgt[base + 1] = w1 * inv; g_wgt[base + 2] = w2 * inv;
        }
        return;
    }
    r -= NB_T3;
    if (r < NB_P2) {
        int b = r >> 10, y = (r >> 6) & 15, x = r & 63;
        int c0 = y * 32, s0 = x * 32;
        int tx = tid & 31, ty = tid >> 5;
        float (*t)[33] = (float(*)[33])sh;
#pragma unroll
        for (int j = ty; j < 32; j += 8)
            t[j][tx] = p2[((size_t)b * D2 + c0 + j) * SS + s0 + tx];
        __syncthreads();
#pragma unroll
        for (int j = ty; j < 32; j += 8)
            g_P2T[((size_t)b * SS + s0 + j) * D2 + c0 + tx] = __float2half_rn(t[tx][j]);
        return;
    }
    r -= NB_P2;
    if (r < NB_P1) {
        int b = r >> 11, y = (r >> 8) & 7, x = r & 255;
        int c0 = y * 32, n0 = x * 32;
        int tx = tid & 31, ty = tid >> 5;
        float (*t)[33] = (float(*)[33])sh;
#pragma unroll
        for (int j = ty; j < 32; j += 8)
            t[j][tx] = p1[((size_t)b * D1 + c0 + j) * NN + n0 + tx];
        __syncthreads();
#pragma unroll
        for (int j = ty; j < 32; j += 8) {
            size_t off = ((size_t)b * NN + n0 + j) * CIN + c0 + tx;
            g_FT[off] = __float2half_rn(t[tx][j]);
        }
        return;
    }
    r -= NB_P1;
    if (r < NB_C0 + NB_C1) {
        const float* src;
        h16* dst;
        int i;
        if (r < NB_C0) { src = w0g; dst = g_W0; i = r * 1024 + tid * 4; }
        else { src = w1g; dst = g_W1; i = (r - NB_C0) * 1024 + tid * 4; }
        float4 v = *(const float4*)(src + i);
        *(uint2*)&dst[i] = make_uint2(
            pack2h(__float2half_rn(v.x), __float2half_rn(v.y)),
            pack2h(__float2half_rn(v.z), __float2half_rn(v.w)));
        return;
    }
    if (tid < 256) {
        g_sum0[tid] = 0.f; g_sum0[tid + 256] = 0.f;
        g_sq0[tid] = 0.f;  g_sq0[tid + 256] = 0.f;
        g_sum1[tid] = 0.f; g_sum1[tid + 256] = 0.f;
        g_sq1[tid] = 0.f;  g_sq1[tid + 256] = 0.f;
    }
}

// ---------------- gather + interpolate -> g_FT[:, :, 256:768] (uint4 vectorized) ----------------
__global__ void gather_kernel() {
    int wglob = blockIdx.x * 8 + (threadIdx.x >> 5);
    int lane = threadIdx.x & 31;
    int b = wglob / NN;
    size_t base = (size_t)wglob * 3;
    int i0 = g_idx[base + 0], i1 = g_idx[base + 1], i2 = g_idx[base + 2];
    float w0 = g_wgt[base + 0], w1 = g_wgt[base + 1], w2 = g_wgt[base + 2];
    const h16* r0 = g_P2T + ((size_t)b * SS + i0) * D2;
    const h16* r1 = g_P2T + ((size_t)b * SS + i1) * D2;
    const h16* r2 = g_P2T + ((size_t)b * SS + i2) * D2;
    size_t dbase = (size_t)wglob * CIN + D1;
#pragma unroll
    for (int c = lane * 8; c < D2; c += 256) {
        uint4 u0 = *(const uint4*)&r0[c];
        uint4 u1 = *(const uint4*)&r1[c];
        uint4 u2 = *(const uint4*)&r2[c];
        uint4 o;
        uint32_t* up0 = (uint32_t*)&u0;
        uint32_t* up1 = (uint32_t*)&u1;
        uint32_t* up2 = (uint32_t*)&u2;
        uint32_t* op = (uint32_t*)&o;
#pragma unroll
        for (int j = 0; j < 4; j++) {
            float2 a = h2f2(up0[j]), d = h2f2(up1[j]), e = h2f2(up2[j]);
            float y0 = w0 * a.x + w1 * d.x + w2 * e.x;
            float y1 = w0 * a.y + w1 * d.y + w2 * e.y;
            op[j] = pack2h(__float2half_rn(y0), __float2half_rn(y1));
        }
        *(uint4*)&g_FT[dbase + c] = o;
    }
}

// ======================= HMMA GEMM 1 (fp16, K-chunk 64, ring-2) =======================
#define T1B 18432                         // 128 rows x 144B (64 fp16 + 8 pad)
#define ST1 (2 * T1B)                     // stage: A, B = 36864
static constexpr int G1_SMEM = 2 * ST1;   // 73728 -> 2 CTAs/SM

__global__ __launch_bounds__(256, 2)
void hmma_gemm1(const h16* __restrict__ Ag, const h16* __restrict__ Bg,
                const float* __restrict__ bias, h16* __restrict__ out) {
    extern __shared__ char smem[];
    const uint32_t sb = smem_u32(smem);
    const int tid = threadIdx.x, lane = tid & 31, wid = tid >> 5;
    const int m0 = blockIdx.x * 128, n0 = blockIdx.y * 128, b = blockIdx.z;
    const int wm = (wid & 3) * 32, wn = (wid >> 2) * 64;

    const h16* Arow = Ag + (size_t)m0 * CIN;
    const h16* Brow = Bg + ((size_t)b * NN + n0) * CIN;

    float acc[2][8][4];
#pragma unroll
    for (int i = 0; i < 2; i++)
#pragma unroll
        for (int j = 0; j < 8; j++)
#pragma unroll
            for (int q = 0; q < 4; q++) acc[i][j][q] = 0.f;

    const int row_l = tid >> 3, seg = tid & 7;
    auto issue = [&](int kc) {
        const int kb = kc * 64;
        const uint32_t sbuf = sb + (kc & 1) * ST1;
#pragma unroll
        for (int t = 0; t < 4; t++) {
            int row = row_l + t * 32;
            uint32_t d = sbuf + row * 144 + seg * 16;
            cpa16(d,       Arow + (size_t)row * CIN + kb + seg * 8);
            cpa16(d + T1B, Brow + (size_t)row * CIN + kb + seg * 8);
        }
        CP_COMMIT();
    };

    const int KT = CIN / 64;   // 12
    issue(0);

    for (int c = 0; c < KT; c++) {
        const int buf = c & 1;
        if (c + 1 < KT) {
            issue(c + 1);
            CP_WAIT(1);
        } else {
            CP_WAIT(0);
        }
        __syncthreads();

        const uint32_t sA = sb + buf * ST1;
        const uint32_t sB = sA + T1B;
#pragma unroll
        for (int ks = 0; ks < 4; ks++) {
            const int k16 = ks * 16;
            uint32_t ah[2][4];
#pragma unroll
            for (int mi = 0; mi < 2; mi++) {
                uint32_t ad = sA + (wm + mi * 16 + (lane & 15)) * 144
                                 + (k16 + ((lane >> 4) << 3)) * 2;
                ldsm4(ah[mi][0], ah[mi][1], ah[mi][2], ah[mi][3], ad);
            }
#pragma unroll
            for (int ng = 0; ng < 4; ng++) {
                uint32_t row = wn + ng * 16 + (lane & 7) + ((lane & 16) >> 1);
                uint32_t col = k16 + (lane & 8);
                uint32_t ad = sB + row * 144 + col * 2;
                uint32_t bh[4];
                ldsm4(bh[0], bh[1], bh[2], bh[3], ad);
#pragma unroll
                for (int mi = 0; mi < 2; mi++) {
                    mma16816(acc[mi][2 * ng],     ah[mi], bh);
                    mma16816(acc[mi][2 * ng + 1], ah[mi], bh + 2);
                }
            }
        }
        __syncthreads();
    }

    // epilogue -> out fp16 (b, m, n) + bias, fused channel stats via atomics
    const int gq = lane >> 2, tq = lane & 3;
#pragma unroll
    for (int mi = 0; mi < 2; mi++) {
        int r0 = m0 + wm + mi * 16 + gq;
        float bv0 = bias[r0], bv1 = bias[r0 + 8];
        h16* o0 = out + ((size_t)b * HH + r0) * NN;
        h16* o1 = o0 + (size_t)8 * NN;
        float s0 = 0.f, q0 = 0.f, s1 = 0.f, q1 = 0.f;
#pragma unroll
        for (int ni = 0; ni < 8; ni++) {
            int cc = n0 + wn + ni * 8 + tq * 2;
            float y0 = acc[mi][ni][0] + bv0, y1 = acc[mi][ni][1] + bv0;
            float y2 = acc[mi][ni][2] + bv1, y3 = acc[mi][ni][3] + bv1;
            *(uint32_t*)&o0[cc] = pack2h(__float2half_rn(y0), __float2half_rn(y1));
            *(uint32_t*)&o1[cc] = pack2h(__float2half_rn(y2), __float2half_rn(y3));
            s0 += y0 + y1; q0 += y0 * y0 + y1 * y1;
            s1 += y2 + y3; q1 += y2 * y2 + y3 * y3;
        }
#pragma unroll
        for (int o = 1; o <= 2; o <<= 1) {
            s0 += __shfl_xor_sync(~0u, s0, o);
            q0 += __shfl_xor_sync(~0u, q0, o);
            s1 += __shfl_xor_sync(~0u, s1, o);
            q1 += __shfl_xor_sync(~0u, q1, o);
        }
        if (tq == 0) {
            atomicAdd(&g_sum0[r0], s0);     atomicAdd(&g_sq0[r0], q0);
            atomicAdd(&g_sum0[r0 + 8], s1); atomicAdd(&g_sq0[r0 + 8], q1);
        }
    }
}

// ======================= HMMA GEMM 2 (fp16, K-chunk 64, in-kernel BN coeffs) =======================
#define AT2 18432                // A stage: 128 x 144B
#define BT2 17408                // B stage: 64 k-rows x 272B
#define SC2_OFF (2 * AT2 + 2 * BT2)                  // 71680
static constexpr int G2_SMEM = SC2_OFF + 2 * HH * 4; // 75776 -> 2 CTAs/SM

__global__ __launch_bounds__(256, 2)
void hmma_gemm2(const h16* __restrict__ Ag,
                const h16* __restrict__ X0,
                const float* __restrict__ gsum, const float* __restrict__ gsq,
                const float* __restrict__ g0, const float* __restrict__ be0,
                const float* __restrict__ bias, float* __restrict__ out) {
    extern __shared__ char smem[];
    const uint32_t sb = smem_u32(smem);
    const int tid = threadIdx.x, lane = tid & 31, wid = tid >> 5;
    const int m0 = blockIdx.x * 128, n0 = blockIdx.y * 128, b = blockIdx.z;
    const int wm = (wid & 3) * 32, wn = (wid >> 2) * 64;

    float* sScale = (float*)(smem + SC2_OFF);
    float* sShift = sScale + HH;

    const h16* Arow = Ag + (size_t)m0 * HH;
    const h16* Xb = X0 + (size_t)b * HH * NN + n0;

    float acc[2][8][4];
#pragma unroll
    for (int i = 0; i < 2; i++)
#pragma unroll
        for (int j = 0; j < 8; j++)
#pragma unroll
            for (int q = 0; q < 4; q++) acc[i][j][q] = 0.f;

    const int brow = tid >> 3, bcol = (tid & 7) * 16;
    uint4 xr[2][2];
    float scl[2], shf[2];

    const int row_l = tid >> 3, seg = tid & 7;
    auto issueA = [&](int kc) {
        const int kb = kc * 64;
        const uint32_t sbuf = sb + (kc & 1) * AT2;
#pragma unroll
        for (int t = 0; t < 4; t++) {
            int row = row_l + t * 32;
            uint32_t d = sbuf + row * 144 + seg * 16;
            cpa16(d, Arow + (size_t)row * HH + kb + seg * 8);
        }
        CP_COMMIT();
    };
    auto loadX = [&](int kb) {
#pragma unroll
        for (int half = 0; half < 2; half++) {
            int k = kb + brow + half * 32;
            const h16* src = Xb + (size_t)k * NN + bcol;
            xr[half][0] = *(const uint4*)src;
            xr[half][1] = *(const uint4*)(src + 8);
            scl[half] = sScale[k];
            shf[half] = sShift[k];
        }
    };

    // prologue: BN coefficients for layer 0 -> smem
    {
        const float inv = 1.f / (float)(BB * NN);
#pragma unroll
        for (int i = tid; i < HH; i += 256) {
            float m = gsum[i] * inv;
            float var = gsq[i] * inv - m * m;
            float sc = g0[i] * rsqrtf(var + 1e-5f);
            sScale[i] = sc;
            sShift[i] = be0[i] - m * sc;
        }
        issueA(0);
        __syncthreads();   // sScale/sShift visible before loadX
        loadX(0);
    }

    const uint32_t sBoff = 2 * AT2;
    const int KT = HH / 64;  // 8
    for (int c = 0; c < KT; c++) {
        const int buf = c & 1;
        // STS-transform chunk c into B buf (64 k-rows x 128 n)
        {
#pragma unroll
            for (int half = 0; half < 2; half++) {
                uint32_t doff = sBoff + buf * BT2 + (brow + half * 32) * 272 + bcol * 2;
                float s = scl[half], h = shf[half];
#pragma unroll
                for (int j = 0; j < 4; j++) {
                    float2 p = h2f2(j < 2 ? (j == 0 ? xr[half][0].x : xr[half][0].z)
                                          : (j == 2 ? xr[half][1].x : xr[half][1].z));
                    float2 q = h2f2(j < 2 ? (j == 0 ? xr[half][0].y : xr[half][0].w)
                                          : (j == 2 ? xr[half][1].y : xr[half][1].w));
                    float y0 = fmaxf(fmaf(p.x, s, h), 0.f);
                    float y1 = fmaxf(fmaf(p.y, s, h), 0.f);
                    float y2 = fmaxf(fmaf(q.x, s, h), 0.f);
                    float y3 = fmaxf(fmaf(q.y, s, h), 0.f);
                    *(uint2*)(smem + doff + j * 8) = make_uint2(
                        pack2h(__float2half_rn(y0), __float2half_rn(y1)),
                        pack2h(__float2half_rn(y2), __float2half_rn(y3)));
                }
            }
        }
        if (c + 1 < KT) {
            issueA(c + 1);
            loadX((c + 1) * 64);
            CP_WAIT(1);
        } else {
            CP_WAIT(0);
        }
        __syncthreads();

        const uint32_t sA = sb + buf * AT2;
        const uint32_t sB = sb + sBoff + buf * BT2;
#pragma unroll
        for (int ks = 0; ks < 4; ks++) {
            const int k16 = ks * 16;
            uint32_t ah[2][4];
#pragma unroll
            for (int mi = 0; mi < 2; mi++) {
                uint32_t ad = sA + (wm + mi * 16 + (lane & 15)) * 144
                                 + (k16 + ((lane >> 4) << 3)) * 2;
                ldsm4(ah[mi][0], ah[mi][1], ah[mi][2], ah[mi][3], ad);
            }
#pragma unroll
            for (int ng = 0; ng < 4; ng++) {
                uint32_t row = k16 + (lane & 7) + (lane & 8);
                uint32_t col = wn + ng * 16 + ((lane >> 4) << 3);
                uint32_t ad = sB + row * 272 + col * 2;
                uint32_t bh[4];
                ldsm4t(bh[0], bh[1], bh[2], bh[3], ad);
#pragma unroll
                for (int mi = 0; mi < 2; mi++) {
                    mma16816(acc[mi][2 * ng],     ah[mi], bh);
                    mma16816(acc[mi][2 * ng + 1], ah[mi], bh + 2);
                }
            }
        }
        __syncthreads();
    }

    const int gq = lane >> 2, tq = lane & 3;
#pragma unroll
    for (int mi = 0; mi < 2; mi++) {
        int r0 = m0 + wm + mi * 16 + gq;
        float bv0 = bias[r0], bv1 = bias[r0 + 8];
        float* o0 = out + ((size_t)b * HH + r0) * NN;
        float* o1 = o0 + (size_t)8 * NN;
        float s0 = 0.f, q0 = 0.f, s1 = 0.f, q1 = 0.f;
#pragma unroll
        for (int ni = 0; ni < 8; ni++) {
            int cc = n0 + wn + ni * 8 + tq * 2;
            float y0 = acc[mi][ni][0] + bv0, y1 = acc[mi][ni][1] + bv0;
            float y2 = acc[mi][ni][2] + bv1, y3 = acc[mi][ni][3] + bv1;
            *(float2*)&o0[cc] = make_float2(y0, y1);
            *(float2*)&o1[cc] = make_float2(y2, y3);
            s0 += y0 + y1; q0 += y0 * y0 + y1 * y1;
            s1 += y2 + y3; q1 += y2 * y2 + y3 * y3;
        }
#pragma unroll
        for (int o = 1; o <= 2; o <<= 1) {
            s0 += __shfl_xor_sync(~0u, s0, o);
            q0 += __shfl_xor_sync(~0u, q0, o);
            s1 += __shfl_xor_sync(~0u, s1, o);
            q1 += __shfl_xor_sync(~0u, q1, o);
        }
        if (tq == 0) {
            atomicAdd(&g_sum1[r0], s0);     atomicAdd(&g_sq1[r0], q0);
            atomicAdd(&g_sum1[r0 + 8], s1); atomicAdd(&g_sq1[r0 + 8], q1);
        }
    }
}

// ---------------- apply BN layer1 (coeffs computed in-kernel) ----------------
__global__ __launch_bounds__(256)
void apply_bn_kernel(float* __restrict__ X,
                     const float* __restrict__ g1, const float* __restrict__ be1) {
    __shared__ float sScale[HH], sShift[HH];
    const float inv = 1.f / (float)(BB * NN);
#pragma unroll
    for (int i = threadIdx.x; i < HH; i += 256) {
        float m = g_sum1[i] * inv;
        float var = g_sq1[i] * inv - m * m;
        float sc = g1[i] * rsqrtf(var + 1e-5f);
        sScale[i] = sc;
        sShift[i] = be1[i] - m * sc;
    }
    __syncthreads();
    const size_t total4 = (size_t)BB * HH * NN / 4;
    for (size_t i = (size_t)blockIdx.x * blockDim.x + threadIdx.x; i < total4;
         i += (size_t)gridDim.x * blockDim.x) {
        float4 v = __ldcs(&((float4*)X)[i]);
        int c = (int)((i * 4) >> 13) & (HH - 1);
        float s = sScale[c], h = sShift[c];
        v.x = fmaxf(fmaf(v.x, s, h), 0.f);
        v.y = fmaxf(fmaf(v.y, s, h), 0.f);
        v.z = fmaxf(fmaf(v.z, s, h), 0.f);
        v.w = fmaxf(fmaf(v.w, s, h), 0.f);
        __stcs(&((float4*)X)[i], v);
    }
}

// ======================= launcher =======================
extern "C" void kernel_launch(void* const* d_in, const int* in_sizes, int n_in,
                              void* d_out, int out_size) {
    const float* xyz1    = (const float*)d_in[0];
    const float* xyz2    = (const float*)d_in[1];
    const float* points1 = (const float*)d_in[2];
    const float* points2 = (const float*)d_in[3];
    const float* w0 = (const float*)d_in[4];
    const float* b0 = (const float*)d_in[5];
    const float* g0 = (const float*)d_in[6];
    const float* be0 = (const float*)d_in[7];
    const float* w1 = (const float*)d_in[8];
    const float* b1 = (const float*)d_in[9];
    const float* g1 = (const float*)d_in[10];
    const float* be1 = (const float*)d_in[11];
    float* out = (float*)d_out;

    float *p_sum0, *p_sq0;
    h16 *p_W0, *p_W1, *p_FT, *p_X0;
    cudaGetSymbolAddress((void**)&p_X0, g_X0);
    cudaGetSymbolAddress((void**)&p_sum0, g_sum0);
    cudaGetSymbolAddress((void**)&p_sq0, g_sq0);
    cudaGetSymbolAddress((void**)&p_W0, g_W0);
    cudaGetSymbolAddress((void**)&p_W1, g_W1);
    cudaGetSymbolAddress((void**)&p_FT, g_FT);

    cudaFuncSetAttribute(hmma_gemm1, cudaFuncAttributeMaxDynamicSharedMemorySize, G1_SMEM);
    cudaFuncSetAttribute(hmma_gemm2, cudaFuncAttributeMaxDynamicSharedMemorySize, G2_SMEM);

    prep_kernel<<<NB_TOTAL, 256>>>(xyz1, xyz2, points1, points2, w0, w1);
    gather_kernel<<<BB * NN / 8, 256>>>();

    hmma_gemm1<<<dim3(HH / 128, NN / 128, BB), 256, G1_SMEM>>>(
        p_W0, p_FT, b0, p_X0);

    hmma_gemm2<<<dim3(HH / 128, NN / 128, BB), 256, G2_SMEM>>>(
        p_W1, p_X0, p_sum0, p_sq0, g0, be0, b1, out);

    apply_bn_kernel<<<4096, 256>>>(out, g1, be1);
}